// round 1
// baseline (speedup 1.0000x reference)
#include <cuda_runtime.h>
#include <math.h>

#define BB 128
#define LL 512
#define DD 128
#define BL (BB*LL)
#define ML 512

// ---------------- scratch (static device globals; no allocations) ----------------
__device__ float g_seqs[BL*DD];
__device__ float g_Q   [BL*DD];
__device__ float g_q   [BL*DD];
__device__ float g_k   [BL*DD];
__device__ float g_v   [BL*DD];
__device__ float g_qp  [BL*DD];
__device__ float g_mha [BL*DD];
__device__ float g_tmp [BL*DD];
__device__ float g_attn[BB*LL*LL];   // 33.5M floats
__device__ float g_E   [BL*ML];      // 33.5M floats
__device__ float g_cape[BL];

// ---------------- warp reductions ----------------
__device__ __forceinline__ float wredsum(float v){
    #pragma unroll
    for (int o=16;o>0;o>>=1) v += __shfl_xor_sync(0xffffffffu, v, o);
    return v;
}
__device__ __forceinline__ float wredmax(float v){
    #pragma unroll
    for (int o=16;o>0;o>>=1) v = fmaxf(v, __shfl_xor_sync(0xffffffffu, v, o));
    return v;
}

// ---------------- embedding gather: seqs = item_emb[log_seqs] * sqrt(D) ----------------
__global__ void embed_k(const float* __restrict__ item, const int* __restrict__ idx,
                        float* __restrict__ out){
    int row  = blockIdx.x*8 + (threadIdx.x>>5);
    int lane = threadIdx.x & 31;
    int id = idx[row];
    float4 v = *(const float4*)(item + (long long)id*DD + lane*4);
    const float s = 11.313708498984760f; // sqrt(128)
    v.x*=s; v.y*=s; v.z*=s; v.w*=s;
    *(float4*)(out + (long long)row*DD + lane*4) = v;
}

// ---------------- layernorm (optionally add per-row cape scalar first) ----------------
template<bool ADDC>
__global__ void ln_k(const float* __restrict__ x, const float* __restrict__ cape,
                     const float* __restrict__ gs, const float* __restrict__ gb,
                     float* __restrict__ y){
    int row  = blockIdx.x*8 + (threadIdx.x>>5);
    int lane = threadIdx.x & 31;
    const float* xr = x + (long long)row*DD;
    float4 v = *(const float4*)(xr + lane*4);
    if (ADDC){ float c = cape[row]; v.x+=c; v.y+=c; v.z+=c; v.w+=c; }
    float m = wredsum(v.x+v.y+v.z+v.w) * (1.0f/DD);
    float dx=v.x-m, dy=v.y-m, dz=v.z-m, dw=v.w-m;
    float var = wredsum(dx*dx+dy*dy+dz*dz+dw*dw) * (1.0f/DD);
    float r = rsqrtf(var + 1e-8f);
    float4 o;
    o.x = dx*r*gs[lane*4+0] + gb[lane*4+0];
    o.y = dy*r*gs[lane*4+1] + gb[lane*4+1];
    o.z = dz*r*gs[lane*4+2] + gb[lane*4+2];
    o.w = dw*r*gs[lane*4+3] + gb[lane*4+3];
    *(float4*)(y + (long long)row*DD + lane*4) = o;
}

// ---------------- causal softmax in-place; masked entries written as exactly 0 ----------------
__global__ void softmax_k(float* __restrict__ attn){
    int row  = blockIdx.x*8 + (threadIdx.x>>5);
    int lane = threadIdx.x & 31;
    int q = row & (LL-1);
    float* p = attn + (long long)row*LL;
    int nv = q+1;
    float vals[16];
    float mx = -3.4e38f;
    #pragma unroll
    for (int t=0;t<16;t++){
        int j = t*32+lane;
        float s = (j<nv) ? p[j] : -3.4e38f;
        vals[t]=s; mx = fmaxf(mx, s);
    }
    mx = wredmax(mx);
    float sum = 0.f;
    #pragma unroll
    for (int t=0;t<16;t++){
        int j = t*32+lane;
        float e = (j<nv) ? expf(vals[t]-mx) : 0.f;
        vals[t]=e; sum += e;
    }
    sum = wredsum(sum);
    float inv = 1.0f/sum;
    #pragma unroll
    for (int t=0;t<16;t++) p[t*32+lane] = vals[t]*inv;
}

// ---------------- CAPE: G=1-sigmoid(attn); P=rev-cumsum; interp gather of E; mean ----------------
__global__ void cape_k(const float* __restrict__ attn, const float* __restrict__ E,
                       float* __restrict__ cape){
    __shared__ float es[8][ML];
    __shared__ float gsm[8][32][17];
    int w    = threadIdx.x>>5;
    int lane = threadIdx.x & 31;
    int row  = blockIdx.x*8 + w;
    const float* ar = attn + (long long)row*LL;
    const float* er = E    + (long long)row*ML;
    #pragma unroll
    for (int t=0;t<16;t++) es[w][t*32+lane] = er[t*32+lane];
    #pragma unroll
    for (int t=0;t<16;t++){
        int j = t*32+lane;
        float a = ar[j];
        float g = 1.0f/(1.0f+expf(a));   // 1 - sigmoid(a)
        gsm[w][j>>4][j&15] = g;
    }
    __syncwarp();
    float cs = 0.f;
    #pragma unroll
    for (int t=0;t<16;t++) cs += gsm[w][lane][t];
    // inclusive suffix scan across lanes
    float sfx = cs;
    #pragma unroll
    for (int off=1;off<32;off<<=1){
        float o = __shfl_down_sync(0xffffffffu, sfx, off);
        if (lane+off < 32) sfx += o;
    }
    float tail = sfx - cs;
    float run = 0.f, acc = 0.f;
    #pragma unroll
    for (int t=15;t>=0;t--){
        run += gsm[w][lane][t];
        float P = run + tail;
        P = fminf(P, (float)(ML-1));
        float Pf = floorf(P);
        float fr = P - Pf;
        int pi = (int)Pf;
        int pc = (int)ceilf(P);
        float ef = es[w][pi];
        float ec = es[w][pc];
        acc += fr*ec + (1.0f-fr)*ef;
    }
    acc = wredsum(acc);
    if (lane==0) cape[row] = acc * (1.0f/LL);
}

// ---------------- final: LN + dot with pos/neg item embeddings ----------------
__global__ void final_k(const float* __restrict__ seqs, const float* __restrict__ item,
                        const float* __restrict__ gs, const float* __restrict__ gb,
                        const int* __restrict__ pos, const int* __restrict__ neg,
                        float* __restrict__ out){
    int row  = blockIdx.x*8 + (threadIdx.x>>5);
    int lane = threadIdx.x & 31;
    const float* xr = seqs + (long long)row*DD;
    float4 v = *(const float4*)(xr + lane*4);
    float m = wredsum(v.x+v.y+v.z+v.w) * (1.0f/DD);
    float dx=v.x-m, dy=v.y-m, dz=v.z-m, dw=v.w-m;
    float var = wredsum(dx*dx+dy*dy+dz*dz+dw*dw) * (1.0f/DD);
    float r = rsqrtf(var + 1e-8f);
    float f0 = dx*r*gs[lane*4+0] + gb[lane*4+0];
    float f1 = dy*r*gs[lane*4+1] + gb[lane*4+1];
    float f2 = dz*r*gs[lane*4+2] + gb[lane*4+2];
    float f3 = dw*r*gs[lane*4+3] + gb[lane*4+3];
    int pi = pos[row], ni = neg[row];
    float4 pe = *(const float4*)(item + (long long)pi*DD + lane*4);
    float4 ne = *(const float4*)(item + (long long)ni*DD + lane*4);
    float dp = f0*pe.x + f1*pe.y + f2*pe.z + f3*pe.w;
    float dn = f0*ne.x + f1*ne.y + f2*ne.z + f3*ne.w;
    dp = wredsum(dp); dn = wredsum(dn);
    if (lane==0){ out[row] = dp; out[BL+row] = dn; }
}

// ---------------- generic SGEMM: C = act(alpha*A.op(B) + bias) + res ----------------
// A: [M,K] row-major. TRANSB: B is [N,K] (C=A.B^T); else B is [K,N] (C=A.B).
// Tiles 128x128x16, 256 threads, 8x8 per-thread micro-tile. M%128==0, N%128==0, K%16==0.
// SKIPUP: skip tiles fully above the causal diagonal. KLIM: limit K loop to m-tile end (A causal-zero).
template<bool TRANSB, int ACT, bool SKIPUP, bool KLIM>
__global__ __launch_bounds__(256)
void gemm_k(const float* __restrict__ A, const float* __restrict__ Bm,
            const float* __restrict__ bias, const float* __restrict__ res,
            float* __restrict__ C, int M, int N, int K,
            long long sA, long long sB, long long sC, float alpha)
{
    if (SKIPUP && (int)blockIdx.x > (int)blockIdx.y) return;
    const int bz = blockIdx.z;
    A  += (long long)bz*sA;
    Bm += (long long)bz*sB;
    C  += (long long)bz*sC;
    if (res) res += (long long)bz*sC;

    __shared__ float As[16][132];
    __shared__ float Bs[16][132];
    const int tid = threadIdx.x;
    const int tx = tid & 15, ty = tid >> 4;
    const int m0 = blockIdx.y*128, n0 = blockIdx.x*128;
    const int kmax = KLIM ? ((m0+128 < K) ? (m0+128) : K) : K;

    float acc[8][8];
    #pragma unroll
    for (int i=0;i<8;i++)
        #pragma unroll
        for (int j=0;j<8;j++) acc[i][j]=0.f;

    for (int k0=0;k0<kmax;k0+=16){
        #pragma unroll
        for (int r=0;r<2;r++){
            int row = r*64 + (tid>>2);
            int c4  = (tid&3)*4;
            float4 a = *(const float4*)(A + (long long)(m0+row)*K + k0 + c4);
            As[c4+0][row]=a.x; As[c4+1][row]=a.y; As[c4+2][row]=a.z; As[c4+3][row]=a.w;
        }
        if (TRANSB){
            #pragma unroll
            for (int r=0;r<2;r++){
                int row = r*64 + (tid>>2);
                int c4  = (tid&3)*4;
                float4 b = *(const float4*)(Bm + (long long)(n0+row)*K + k0 + c4);
                Bs[c4+0][row]=b.x; Bs[c4+1][row]=b.y; Bs[c4+2][row]=b.z; Bs[c4+3][row]=b.w;
            }
        } else {
            #pragma unroll
            for (int r=0;r<2;r++){
                int idx = r*256 + tid;
                int kk  = idx >> 5;
                int c4  = (idx & 31)*4;
                float4 b = *(const float4*)(Bm + (long long)(k0+kk)*N + n0 + c4);
                *(float4*)&Bs[kk][c4] = b;
            }
        }
        __syncthreads();
        #pragma unroll
        for (int kk=0;kk<16;kk++){
            float a[8], b[8];
            *(float4*)&a[0] = *(const float4*)&As[kk][ty*8];
            *(float4*)&a[4] = *(const float4*)&As[kk][ty*8+4];
            *(float4*)&b[0] = *(const float4*)&Bs[kk][tx*8];
            *(float4*)&b[4] = *(const float4*)&Bs[kk][tx*8+4];
            #pragma unroll
            for (int i=0;i<8;i++)
                #pragma unroll
                for (int j=0;j<8;j++)
                    acc[i][j] = fmaf(a[i], b[j], acc[i][j]);
        }
        __syncthreads();
    }

    #pragma unroll
    for (int i=0;i<8;i++){
        long long m = m0 + ty*8 + i;
        float* crow = C + m*(long long)N;
        const float* rrow = res ? (res + m*(long long)N) : nullptr;
        #pragma unroll
        for (int jq=0;jq<2;jq++){
            float t[4];
            #pragma unroll
            for (int u=0;u<4;u++){
                int n = n0 + tx*8 + jq*4 + u;
                float vv = acc[i][jq*4+u]*alpha;
                if (bias) vv += bias[n];
                if (ACT==1) vv = fmaxf(vv, 0.f);
                if (ACT==2) vv = vv/(1.0f+expf(-vv));
                if (rrow) vv += rrow[n];
                t[u]=vv;
            }
            float4 o; o.x=t[0]; o.y=t[1]; o.z=t[2]; o.w=t[3];
            *(float4*)(crow + n0 + tx*8 + jq*4) = o;
        }
    }
}

// ---------------- host orchestration ----------------
extern "C" void kernel_launch(void* const* d_in, const int* in_sizes, int n_in,
                              void* d_out, int out_size){
    (void)in_sizes; (void)n_in; (void)out_size;
    const float* item   = (const float*)d_in[0];
    const float* posemb = (const float*)d_in[1];
    const float* pre_w  = (const float*)d_in[2];
    const float* pre_b  = (const float*)d_in[3];
    const float* ln1_s  = (const float*)d_in[4];
    const float* ln1_b  = (const float*)d_in[5];
    const float* in_w   = (const float*)d_in[6];
    const float* in_b   = (const float*)d_in[7];
    const float* out_w  = (const float*)d_in[8];
    const float* out_b  = (const float*)d_in[9];
    const float* ln2_s  = (const float*)d_in[10];
    const float* ln2_b  = (const float*)d_in[11];
    const float* c1_w   = (const float*)d_in[12];
    const float* c1_b   = (const float*)d_in[13];
    const float* c2_w   = (const float*)d_in[14];
    const float* c2_b   = (const float*)d_in[15];
    const float* lnf_s  = (const float*)d_in[16];
    const float* lnf_b  = (const float*)d_in[17];
    // d_in[18] = user_ids (unused by the reference)
    const int* logs = (const int*)d_in[19];
    const int* poss = (const int*)d_in[20];
    const int* negs = (const int*)d_in[21];
    float* out = (float*)d_out;

    float *seqs,*Q,*q,*k,*v,*qp,*mha,*tmp,*attn,*E,*cape;
    cudaGetSymbolAddress((void**)&seqs, g_seqs);
    cudaGetSymbolAddress((void**)&Q,    g_Q);
    cudaGetSymbolAddress((void**)&q,    g_q);
    cudaGetSymbolAddress((void**)&k,    g_k);
    cudaGetSymbolAddress((void**)&v,    g_v);
    cudaGetSymbolAddress((void**)&qp,   g_qp);
    cudaGetSymbolAddress((void**)&mha,  g_mha);
    cudaGetSymbolAddress((void**)&tmp,  g_tmp);
    cudaGetSymbolAddress((void**)&attn, g_attn);
    cudaGetSymbolAddress((void**)&E,    g_E);
    cudaGetSymbolAddress((void**)&cape, g_cape);

    const int ROWB = BL/8;          // warp-per-row kernels, 8 rows per 256-thread block
    const float scale = 0.08838834764831845f; // 1/sqrt(128)

    embed_k<<<ROWB,256>>>(item, logs, seqs);

    for (int i=0;i<2;i++){
        const float* wq = in_w + (long long)i*3*DD*DD;
        const float* wk = wq + DD*DD;
        const float* wv = wk + DD*DD;
        const float* bq = in_b + (long long)i*3*DD;
        const float* bk = bq + DD;
        const float* bv = bk + DD;

        ln_k<false><<<ROWB,256>>>(seqs, nullptr, ln1_s+i*DD, ln1_b+i*DD, Q);

        dim3 gl(1, BL/128);
        gemm_k<true,0,false,false><<<gl,256>>>(Q,    wq,    bq,    nullptr, q,  BL, DD, DD, 0,0,0, 1.f);
        gemm_k<true,0,false,false><<<gl,256>>>(seqs, wk,    bk,    nullptr, k,  BL, DD, DD, 0,0,0, 1.f);
        gemm_k<true,0,false,false><<<gl,256>>>(seqs, wv,    bv,    nullptr, v,  BL, DD, DD, 0,0,0, 1.f);
        gemm_k<true,2,false,false><<<gl,256>>>(Q,    pre_w, pre_b, nullptr, qp, BL, DD, DD, 0,0,0, 1.f);

        // scores = q.k^T * scale  (skip fully-masked upper tiles)
        dim3 gsc(4,4,BB);
        gemm_k<true,0,true,false><<<gsc,256>>>(q, k, nullptr, nullptr, attn,
            LL, LL, DD, (long long)LL*DD, (long long)LL*DD, (long long)LL*LL, scale);
        softmax_k<<<ROWB,256>>>(attn);

        // mha = attn.v  (K-loop limited by causal zeros)
        dim3 gav(1,4,BB);
        gemm_k<false,0,false,true><<<gav,256>>>(attn, v, nullptr, nullptr, mha,
            LL, DD, LL, (long long)LL*LL, (long long)LL*DD, (long long)LL*DD, 1.f);

        // seqs = Q + mha.out_w^T + out_b
        gemm_k<true,0,false,false><<<gl,256>>>(mha, out_w+(long long)i*DD*DD, out_b+i*DD,
                                               Q, seqs, BL, DD, DD, 0,0,0, 1.f);

        // E = qp @ pos_emb   [BL, 512]
        dim3 ge(4, BL/128);
        gemm_k<false,0,false,false><<<ge,256>>>(qp, posemb, nullptr, nullptr, E,
                                                BL, ML, DD, 0,0,0, 1.f);
        cape_k<<<ROWB,256>>>(attn, E, cape);

        // seqs = LN2(seqs + cape)  -> X (stored in Q buffer)
        ln_k<true><<<ROWB,256>>>(seqs, cape, ln2_s+i*DD, ln2_b+i*DD, Q);

        // FFN: h = relu(X.c1^T + b1); seqs = X + h.c2^T + b2
        gemm_k<true,1,false,false><<<gl,256>>>(Q,   c1_w+(long long)i*DD*DD, c1_b+i*DD,
                                               nullptr, tmp, BL, DD, DD, 0,0,0, 1.f);
        gemm_k<true,0,false,false><<<gl,256>>>(tmp, c2_w+(long long)i*DD*DD, c2_b+i*DD,
                                               Q, seqs, BL, DD, DD, 0,0,0, 1.f);
    }

    final_k<<<ROWB,256>>>(seqs, item, lnf_s, lnf_b, poss, negs, out);
}

// round 2
// speedup vs baseline: 1.9692x; 1.9692x over previous
#include <cuda_runtime.h>
#include <math.h>

#define BB 128
#define LL 512
#define DD 128
#define BL (BB*LL)
#define ML 512

// ---------------- scratch (static device globals; no allocations) ----------------
__device__ float g_seqs[BL*DD];
__device__ float g_Q   [BL*DD];
__device__ float g_q   [BL*DD];
__device__ float g_k   [BL*DD];
__device__ float g_v   [BL*DD];
__device__ float g_qp  [BL*DD];
__device__ float g_mha [BL*DD];
__device__ float g_tmp [BL*DD];
__device__ float g_attn[BB*LL*LL];
__device__ float g_E   [BL*ML];
__device__ float g_cape[BL];

// ---------------- warp reductions ----------------
__device__ __forceinline__ float wredsum(float v){
    #pragma unroll
    for (int o=16;o>0;o>>=1) v += __shfl_xor_sync(0xffffffffu, v, o);
    return v;
}
__device__ __forceinline__ float wredmax(float v){
    #pragma unroll
    for (int o=16;o>0;o>>=1) v = fmaxf(v, __shfl_xor_sync(0xffffffffu, v, o));
    return v;
}

__device__ __forceinline__ unsigned f2tf(float f){
    unsigned r; asm("cvt.rna.tf32.f32 %0, %1;" : "=r"(r) : "f"(f)); return r;
}

__device__ __forceinline__ void mma_tf32(float* d, const unsigned* a, const unsigned* b){
    asm volatile(
        "mma.sync.aligned.m16n8k8.row.col.f32.tf32.tf32.f32 "
        "{%0,%1,%2,%3},{%4,%5,%6,%7},{%8,%9},{%0,%1,%2,%3};"
        : "+f"(d[0]),"+f"(d[1]),"+f"(d[2]),"+f"(d[3])
        : "r"(a[0]),"r"(a[1]),"r"(a[2]),"r"(a[3]), "r"(b[0]),"r"(b[1]));
}

// ---------------- embedding gather: seqs = item_emb[log_seqs] * sqrt(D) ----------------
__global__ void embed_k(const float* __restrict__ item, const int* __restrict__ idx,
                        float* __restrict__ out){
    int row  = blockIdx.x*8 + (threadIdx.x>>5);
    int lane = threadIdx.x & 31;
    int id = idx[row];
    float4 v = *(const float4*)(item + (long long)id*DD + lane*4);
    const float s = 11.313708498984760f; // sqrt(128)
    v.x*=s; v.y*=s; v.z*=s; v.w*=s;
    *(float4*)(out + (long long)row*DD + lane*4) = v;
}

// ---------------- layernorm (optionally add per-row cape scalar first) ----------------
template<bool ADDC>
__global__ void ln_k(const float* __restrict__ x, const float* __restrict__ cape,
                     const float* __restrict__ gs, const float* __restrict__ gb,
                     float* __restrict__ y){
    int row  = blockIdx.x*8 + (threadIdx.x>>5);
    int lane = threadIdx.x & 31;
    const float* xr = x + (long long)row*DD;
    float4 v = *(const float4*)(xr + lane*4);
    if (ADDC){ float c = cape[row]; v.x+=c; v.y+=c; v.z+=c; v.w+=c; }
    float m = wredsum(v.x+v.y+v.z+v.w) * (1.0f/DD);
    float dx=v.x-m, dy=v.y-m, dz=v.z-m, dw=v.w-m;
    float var = wredsum(dx*dx+dy*dy+dz*dz+dw*dw) * (1.0f/DD);
    float r = rsqrtf(var + 1e-8f);
    float4 o;
    o.x = dx*r*gs[lane*4+0] + gb[lane*4+0];
    o.y = dy*r*gs[lane*4+1] + gb[lane*4+1];
    o.z = dz*r*gs[lane*4+2] + gb[lane*4+2];
    o.w = dw*r*gs[lane*4+3] + gb[lane*4+3];
    *(float4*)(y + (long long)row*DD + lane*4) = o;
}

// ---------------- fused causal softmax + CAPE ----------------
// Reads raw scores from attn, writes normalized probs back (masked = exact 0),
// then computes G=1-sigmoid(p), reversed cumsum P, interpolated gather of E, mean.
__global__ void softcape_k(float* __restrict__ attn, const float* __restrict__ E,
                           float* __restrict__ cape){
    __shared__ float es[8][ML];
    __shared__ float gsm[8][32][17];
    int w    = threadIdx.x>>5;
    int lane = threadIdx.x & 31;
    int row  = blockIdx.x*8 + w;
    int qi = row & (LL-1);
    float* p = attn + (long long)row*LL;
    const float* er = E + (long long)row*ML;
    #pragma unroll
    for (int t=0;t<16;t++) es[w][t*32+lane] = er[t*32+lane];

    int nv = qi+1;
    float vals[16];
    float mx = -3.4e38f;
    #pragma unroll
    for (int t=0;t<16;t++){
        int j = t*32+lane;
        float s = (j<nv) ? p[j] : -3.4e38f;
        vals[t]=s; mx = fmaxf(mx, s);
    }
    mx = wredmax(mx);
    float sum = 0.f;
    #pragma unroll
    for (int t=0;t<16;t++){
        int j = t*32+lane;
        float e = (j<nv) ? expf(vals[t]-mx) : 0.f;
        vals[t]=e; sum += e;
    }
    sum = wredsum(sum);
    float inv = 1.0f/sum;
    #pragma unroll
    for (int t=0;t<16;t++){
        int j = t*32+lane;
        float pv = vals[t]*inv;
        p[j] = pv;
        float g = 1.0f/(1.0f+expf(pv));   // 1 - sigmoid(pv); masked pv=0 -> 0.5 (matches ref)
        gsm[w][j>>4][j&15] = g;
    }
    __syncwarp();
    float cs = 0.f;
    #pragma unroll
    for (int t=0;t<16;t++) cs += gsm[w][lane][t];
    float sfx = cs;
    #pragma unroll
    for (int off=1;off<32;off<<=1){
        float o = __shfl_down_sync(0xffffffffu, sfx, off);
        if (lane+off < 32) sfx += o;
    }
    float tail = sfx - cs;
    float run = 0.f, acc = 0.f;
    #pragma unroll
    for (int t=15;t>=0;t--){
        run += gsm[w][lane][t];
        float P = run + tail;
        P = fminf(P, (float)(ML-1));
        float Pf = floorf(P);
        float fr = P - Pf;
        int pi = (int)Pf;
        int pc = (int)ceilf(P);
        float ef = es[w][pi];
        float ec = es[w][pc];
        acc += fr*ec + (1.0f-fr)*ef;
    }
    acc = wredsum(acc);
    if (lane==0) cape[row] = acc * (1.0f/LL);
}

// ---------------- final: LN + dot with pos/neg item embeddings ----------------
__global__ void final_k(const float* __restrict__ seqs, const float* __restrict__ item,
                        const float* __restrict__ gs, const float* __restrict__ gb,
                        const int* __restrict__ pos, const int* __restrict__ neg,
                        float* __restrict__ out){
    int row  = blockIdx.x*8 + (threadIdx.x>>5);
    int lane = threadIdx.x & 31;
    const float* xr = seqs + (long long)row*DD;
    float4 v = *(const float4*)(xr + lane*4);
    float m = wredsum(v.x+v.y+v.z+v.w) * (1.0f/DD);
    float dx=v.x-m, dy=v.y-m, dz=v.z-m, dw=v.w-m;
    float var = wredsum(dx*dx+dy*dy+dz*dz+dw*dw) * (1.0f/DD);
    float r = rsqrtf(var + 1e-8f);
    float f0 = dx*r*gs[lane*4+0] + gb[lane*4+0];
    float f1 = dy*r*gs[lane*4+1] + gb[lane*4+1];
    float f2 = dz*r*gs[lane*4+2] + gb[lane*4+2];
    float f3 = dw*r*gs[lane*4+3] + gb[lane*4+3];
    int pi = pos[row], ni = neg[row];
    float4 pe = *(const float4*)(item + (long long)pi*DD + lane*4);
    float4 ne = *(const float4*)(item + (long long)ni*DD + lane*4);
    float dp = f0*pe.x + f1*pe.y + f2*pe.z + f3*pe.w;
    float dn = f0*ne.x + f1*ne.y + f2*ne.z + f3*ne.w;
    dp = wredsum(dp); dn = wredsum(dn);
    if (lane==0){ out[row] = dp; out[BL+row] = dn; }
}

// ---------------- TF32 tensor-core GEMM: C = act(alpha*A.op(B) + bias) + res ----------------
// A: [M,K] row-major. TRANSB: B is [N,K] (C=A.B^T); else B is [K,N] (C=A.B).
// Block tile 128x128x16, 256 threads (8 warps, each 64x32 via m16n8k8 tf32 mma).
// SKIPUP: skip tiles fully above causal diagonal. KLIM: limit K loop to m0+128 (A causal-zero).
template<bool TRANSB, int ACT, bool SKIPUP, bool KLIM>
__global__ __launch_bounds__(256,2)
void gemm_t(const float* __restrict__ A, const float* __restrict__ Bm,
            const float* __restrict__ bias, const float* __restrict__ res,
            float* __restrict__ C, int M, int N, int K,
            long long sA, long long sB, long long sC, float alpha)
{
    if (SKIPUP && (int)blockIdx.x > (int)blockIdx.y) return;
    const int bz = blockIdx.z;
    A  += (long long)bz*sA;
    Bm += (long long)bz*sB;
    C  += (long long)bz*sC;
    if (res) res += (long long)bz*sC;

    __shared__ unsigned As[16][136];   // k-major: As[k][m], stride 136 -> conflict-free frags
    __shared__ unsigned Bs[16][136];   // k-major: Bs[k][n]

    const int tid  = threadIdx.x;
    const int warp = tid >> 5;
    const int lane = tid & 31;
    const int wm = (warp & 1) * 64;    // warp M offset within block tile
    const int wn = (warp >> 1) * 32;   // warp N offset
    const int m0 = blockIdx.y*128, n0 = blockIdx.x*128;
    const int kmax = KLIM ? ((m0+128 < K) ? (m0+128) : K) : K;

    float acc[4][4][4];
    #pragma unroll
    for (int i=0;i<4;i++)
        #pragma unroll
        for (int j=0;j<4;j++)
            #pragma unroll
            for (int r=0;r<4;r++) acc[i][j][r]=0.f;

    const int ldrow = tid >> 2;          // 0..63
    const int ldc4  = (tid & 3) * 4;     // 0,4,8,12

    for (int k0=0; k0<kmax; k0+=16){
        #pragma unroll
        for (int r=0;r<2;r++){
            int row = r*64 + ldrow;
            float4 a = *(const float4*)(A + (long long)(m0+row)*K + k0 + ldc4);
            As[ldc4+0][row]=f2tf(a.x); As[ldc4+1][row]=f2tf(a.y);
            As[ldc4+2][row]=f2tf(a.z); As[ldc4+3][row]=f2tf(a.w);
        }
        if (TRANSB){
            #pragma unroll
            for (int r=0;r<2;r++){
                int row = r*64 + ldrow;
                float4 b = *(const float4*)(Bm + (long long)(n0+row)*K + k0 + ldc4);
                Bs[ldc4+0][row]=f2tf(b.x); Bs[ldc4+1][row]=f2tf(b.y);
                Bs[ldc4+2][row]=f2tf(b.z); Bs[ldc4+3][row]=f2tf(b.w);
            }
        } else {
            #pragma unroll
            for (int r=0;r<2;r++){
                int idx = r*256 + tid;
                int kk  = idx >> 5;
                int c4  = (idx & 31)*4;
                float4 b = *(const float4*)(Bm + (long long)(k0+kk)*N + n0 + c4);
                uint4 u; u.x=f2tf(b.x); u.y=f2tf(b.y); u.z=f2tf(b.z); u.w=f2tf(b.w);
                *(uint4*)&Bs[kk][c4] = u;
            }
        }
        __syncthreads();

        #pragma unroll
        for (int ks=0; ks<2; ks++){
            const int kb = ks*8;
            const int ar = (lane>>2);
            const int ac = kb + (lane&3);
            unsigned af[4][4], bf[4][2];
            #pragma unroll
            for (int mi=0;mi<4;mi++){
                int r = wm + mi*16 + ar;
                af[mi][0]=As[ac  ][r];   af[mi][1]=As[ac  ][r+8];
                af[mi][2]=As[ac+4][r];   af[mi][3]=As[ac+4][r+8];
            }
            #pragma unroll
            for (int ni=0;ni<4;ni++){
                int n = wn + ni*8 + ar;
                bf[ni][0]=Bs[ac  ][n];
                bf[ni][1]=Bs[ac+4][n];
            }
            #pragma unroll
            for (int mi=0;mi<4;mi++)
                #pragma unroll
                for (int ni=0;ni<4;ni++)
                    mma_tf32(acc[mi][ni], af[mi], bf[ni]);
        }
        __syncthreads();
    }

    // epilogue
    const int er = lane>>2;
    const int ec = (lane&3)*2;
    #pragma unroll
    for (int mi=0;mi<4;mi++){
        #pragma unroll
        for (int half=0; half<2; half++){
            long long gm = m0 + wm + mi*16 + er + half*8;
            float* crow = C + gm*(long long)N;
            const float* rrow = res ? (res + gm*(long long)N) : nullptr;
            #pragma unroll
            for (int ni=0;ni<4;ni++){
                int gn = n0 + wn + ni*8 + ec;
                float v0 = acc[mi][ni][half*2+0]*alpha;
                float v1 = acc[mi][ni][half*2+1]*alpha;
                if (bias){ v0 += bias[gn]; v1 += bias[gn+1]; }
                if (ACT==1){ v0 = fmaxf(v0,0.f); v1 = fmaxf(v1,0.f); }
                if (ACT==2){ v0 = v0/(1.0f+expf(-v0)); v1 = v1/(1.0f+expf(-v1)); }
                if (rrow){ v0 += rrow[gn]; v1 += rrow[gn+1]; }
                float2 o; o.x=v0; o.y=v1;
                *(float2*)(crow + gn) = o;
            }
        }
    }
}

// ---------------- host orchestration ----------------
extern "C" void kernel_launch(void* const* d_in, const int* in_sizes, int n_in,
                              void* d_out, int out_size){
    (void)in_sizes; (void)n_in; (void)out_size;
    const float* item   = (const float*)d_in[0];
    const float* posemb = (const float*)d_in[1];
    const float* pre_w  = (const float*)d_in[2];
    const float* pre_b  = (const float*)d_in[3];
    const float* ln1_s  = (const float*)d_in[4];
    const float* ln1_b  = (const float*)d_in[5];
    const float* in_w   = (const float*)d_in[6];
    const float* in_b   = (const float*)d_in[7];
    const float* out_w  = (const float*)d_in[8];
    const float* out_b  = (const float*)d_in[9];
    const float* ln2_s  = (const float*)d_in[10];
    const float* ln2_b  = (const float*)d_in[11];
    const float* c1_w   = (const float*)d_in[12];
    const float* c1_b   = (const float*)d_in[13];
    const float* c2_w   = (const float*)d_in[14];
    const float* c2_b   = (const float*)d_in[15];
    const float* lnf_s  = (const float*)d_in[16];
    const float* lnf_b  = (const float*)d_in[17];
    const int* logs = (const int*)d_in[19];
    const int* poss = (const int*)d_in[20];
    const int* negs = (const int*)d_in[21];
    float* out = (float*)d_out;

    float *seqs,*Q,*q,*k,*v,*qp,*mha,*tmp,*attn,*E,*cape;
    cudaGetSymbolAddress((void**)&seqs, g_seqs);
    cudaGetSymbolAddress((void**)&Q,    g_Q);
    cudaGetSymbolAddress((void**)&q,    g_q);
    cudaGetSymbolAddress((void**)&k,    g_k);
    cudaGetSymbolAddress((void**)&v,    g_v);
    cudaGetSymbolAddress((void**)&qp,   g_qp);
    cudaGetSymbolAddress((void**)&mha,  g_mha);
    cudaGetSymbolAddress((void**)&tmp,  g_tmp);
    cudaGetSymbolAddress((void**)&attn, g_attn);
    cudaGetSymbolAddress((void**)&E,    g_E);
    cudaGetSymbolAddress((void**)&cape, g_cape);

    const int ROWB = BL/8;
    const float scale = 0.08838834764831845f; // 1/sqrt(128)

    embed_k<<<ROWB,256>>>(item, logs, seqs);

    for (int i=0;i<2;i++){
        const float* wq = in_w + (long long)i*3*DD*DD;
        const float* wk = wq + DD*DD;
        const float* wv = wk + DD*DD;
        const float* bq = in_b + (long long)i*3*DD;
        const float* bk = bq + DD;
        const float* bv = bk + DD;

        ln_k<false><<<ROWB,256>>>(seqs, nullptr, ln1_s+i*DD, ln1_b+i*DD, Q);

        dim3 gl(1, BL/128);
        gemm_t<true,0,false,false><<<gl,256>>>(Q,    wq,    bq,    nullptr, q,  BL, DD, DD, 0,0,0, 1.f);
        gemm_t<true,0,false,false><<<gl,256>>>(seqs, wk,    bk,    nullptr, k,  BL, DD, DD, 0,0,0, 1.f);
        gemm_t<true,0,false,false><<<gl,256>>>(seqs, wv,    bv,    nullptr, v,  BL, DD, DD, 0,0,0, 1.f);
        gemm_t<true,2,false,false><<<gl,256>>>(Q,    pre_w, pre_b, nullptr, qp, BL, DD, DD, 0,0,0, 1.f);

        // scores = q.k^T * scale  (skip fully-masked upper tiles)
        dim3 gsc(4,4,BB);
        gemm_t<true,0,true,false><<<gsc,256>>>(q, k, nullptr, nullptr, attn,
            LL, LL, DD, (long long)LL*DD, (long long)LL*DD, (long long)LL*LL, scale);

        // E = qp @ pos_emb   [BL, 512]
        dim3 ge(4, BL/128);
        gemm_t<false,0,false,false><<<ge,256>>>(qp, posemb, nullptr, nullptr, E,
                                                BL, ML, DD, 0,0,0, 1.f);

        // fused softmax + CAPE (writes normalized attn + per-row cape scalar)
        softcape_k<<<ROWB,256>>>(attn, E, cape);

        // mha = attn.v  (K-loop limited by causal zeros)
        dim3 gav(1,4,BB);
        gemm_t<false,0,false,true><<<gav,256>>>(attn, v, nullptr, nullptr, mha,
            LL, DD, LL, (long long)LL*LL, (long long)LL*DD, (long long)LL*DD, 1.f);

        // seqs = Q + mha.out_w^T + out_b
        gemm_t<true,0,false,false><<<gl,256>>>(mha, out_w+(long long)i*DD*DD, out_b+i*DD,
                                               Q, seqs, BL, DD, DD, 0,0,0, 1.f);

        // seqs = LN2(seqs + cape)  -> X (stored in Q buffer)
        ln_k<true><<<ROWB,256>>>(seqs, cape, ln2_s+i*DD, ln2_b+i*DD, Q);

        // FFN: h = relu(X.c1^T + b1); seqs = X + h.c2^T + b2
        gemm_t<true,1,false,false><<<gl,256>>>(Q,   c1_w+(long long)i*DD*DD, c1_b+i*DD,
                                               nullptr, tmp, BL, DD, DD, 0,0,0, 1.f);
        gemm_t<true,0,false,false><<<gl,256>>>(tmp, c2_w+(long long)i*DD*DD, c2_b+i*DD,
                                               Q, seqs, BL, DD, DD, 0,0,0, 1.f);
    }

    final_k<<<ROWB,256>>>(seqs, item, lnf_s, lnf_b, poss, negs, out);
}